// round 13
// baseline (speedup 1.0000x reference)
#include <cuda_runtime.h>
#include <cuda_fp16.h>

#define EPSV 1e-5f

// ---------------- device scratch ----------------
__device__ __align__(16) unsigned short g_W1h[36 * 17 * 16 * 24];   // fp16
__device__ __align__(16) unsigned short g_W2h[153 * 6 * 16 * 24];   // fp16
__device__ __align__(16) unsigned short g_W3t[30 * 16 * 24];        // fp16 f3 tiles
__device__ __align__(16) unsigned short g_W4f[12 * 16 * 24];        // fp16 f4 tiles [ti=dk*4+mt]
__device__ float g_B1[272];
__device__ float g_B2[96];
__device__ float g_B3[16];
__device__ float g_B4[64];
__device__ __align__(16) unsigned short g_Ph[16 * 2048 * 64];
__device__ __align__(16) unsigned short g_Pl[16 * 2048 * 64];
__device__ __align__(16) unsigned short g_f1h[16 * 272 * 2048];     // f1 single fp16
__device__ float g_f2[16 * 96 * 2048];    // K-split partial 0 (with bias)
__device__ float g_f2b[16 * 96 * 2048];   // K-split partial 1

__constant__ int c_part_of[17] = {1,2,3,1,1,4,4,5,5,2,2,3,3,0,0,0,0};
__constant__ int c_idx_of[17]  = {0,0,0,1,2,0,1,0,1,1,2,1,2,0,1,2,3};
__constant__ int c_len_of[6]   = {4,3,3,3,2,2};

// ---------------- helpers ----------------
__device__ __forceinline__ void split_fp16(float x, unsigned short& h, unsigned short& l) {
    __half hh = __float2half_rn(x);
    float r = x - __half2float(hh);
    __half ll = __float2half_rn(r);
    h = __half_as_ushort(hh); l = __half_as_ushort(ll);
}
__device__ __forceinline__ void ldsm4(unsigned r[4], const void* p) {
    unsigned a = (unsigned)__cvta_generic_to_shared(p);
    asm volatile("ldmatrix.sync.aligned.m8n8.x4.shared.b16 {%0,%1,%2,%3},[%4];"
                 : "=r"(r[0]), "=r"(r[1]), "=r"(r[2]), "=r"(r[3]) : "r"(a));
}
__device__ __forceinline__ void mma_fp16(float* c, const unsigned* a, unsigned b0, unsigned b1) {
    asm volatile("mma.sync.aligned.m16n8k16.row.col.f32.f16.f16.f32 "
                 "{%0,%1,%2,%3},{%4,%5,%6,%7},{%8,%9},{%0,%1,%2,%3};"
                 : "+f"(c[0]), "+f"(c[1]), "+f"(c[2]), "+f"(c[3])
                 : "r"(a[0]), "r"(a[1]), "r"(a[2]), "r"(a[3]), "r"(b0), "r"(b1));
}
__device__ __forceinline__ void cpa16(void* dst, const void* src) {
    unsigned d = (unsigned)__cvta_generic_to_shared(dst);
    asm volatile("cp.async.cg.shared.global [%0], [%1], 16;" :: "r"(d), "l"(src));
}
__device__ __forceinline__ void cpa16z(void* dst, const void* src, bool valid) {
    unsigned d = (unsigned)__cvta_generic_to_shared(dst);
    int sz = valid ? 16 : 0;
    asm volatile("cp.async.cg.shared.global [%0], [%1], 16, %2;" :: "r"(d), "l"(src), "r"(sz));
}
#define CP_COMMIT() asm volatile("cp.async.commit_group;")
#define CP_WAIT0()  asm volatile("cp.async.wait_group 0;")

// ---------------- fused prep (627 blocks x 256 thr) ----------------
__global__ void prepAll(const float* __restrict__ poses,
                        const float* __restrict__ A1, const float* __restrict__ w1,
                        const float* __restrict__ b1, const float* __restrict__ g1,
                        const float* __restrict__ be1, const float* __restrict__ m1,
                        const float* __restrict__ v1,
                        const float* __restrict__ A2, const float* __restrict__ w2,
                        const float* __restrict__ b2, const float* __restrict__ g2,
                        const float* __restrict__ be2, const float* __restrict__ m2,
                        const float* __restrict__ v2,
                        const float* __restrict__ w3, const float* __restrict__ b3,
                        const float* __restrict__ g3, const float* __restrict__ be3,
                        const float* __restrict__ m3, const float* __restrict__ v3,
                        const float* __restrict__ w4, const float* __restrict__ b4,
                        const float* __restrict__ g4, const float* __restrict__ be4,
                        const float* __restrict__ m4, const float* __restrict__ v4) {
    const int bid = blockIdx.x;
    if (bid < 256) {
        const int n = bid >> 4, tb = (bid & 15) * 128;
        for (int idx = threadIdx.x; idx < 128 * 64; idx += 256) {
            int tl = idx >> 6, col = idx & 63;
            int t = tb + tl;
            float v = (col < 51) ? poses[((size_t)n * 2048 + t) * 51 + col] : 0.f;
            unsigned short h, l; split_fp16(v, h, l);
            size_t o = ((size_t)n * 2048 + t) * 64 + col;
            g_Ph[o] = h; g_Pl[o] = l;
        }
    } else if (bid < 528) {
        int cw = bid - 256;
        int c = cw / 17, w = cw % 17;
        int mt = cw >> 4, row = cw & 15;
        float s = g1[cw] * rsqrtf(v1[cw] + EPSV);
        for (int e = threadIdx.x; e < 36 * 24; e += 256) {
            int it = e / 24, col = e % 24;
            int dt = it >> 2, rc = it & 3;
            int r = rc * 16 + col;
            float val = 0.f;
            if (col < 16 && r < 51) {
                int u = r / 3, ci = r % 3;
                for (int k = 0; k < 5; k++)
                    for (int dv = 0; dv < 5; dv++) {
                        int v = u - dv + 2;
                        if (v >= 0 && v < 17)
                            val += A1[(k * 17 + v) * 17 + w] *
                                   w1[(((k * 16 + c) * 3 + ci) * 9 + dt) * 5 + dv];
                    }
                val *= s;
            }
            g_W1h[((it * 17 + mt) * 16 + row) * 24 + col] =
                __half_as_ushort(__float2half_rn(val));
        }
        if (threadIdx.x == 0) {
            float bias = 0.f;
            for (int k = 0; k < 5; k++) {
                float sa = 0.f;
                for (int v = 0; v < 17; v++) sa += A1[(k * 17 + v) * 17 + w];
                bias += b1[k * 16 + c] * sa;
            }
            g_B1[cw] = (bias - m1[cw]) * s + be1[cw];
        }
    } else if (bid < 624) {
        int cw = bid - 528;
        int c = cw / 6, w = cw % 6;
        int mt = cw >> 4, row = cw & 15;
        float s = g2[cw] * rsqrtf(v2[cw] + EPSV);
        for (int e = threadIdx.x; e < 153 * 24; e += 256) {
            int it = e / 24, col = e % 24;
            int cc = it / 9, dt = it % 9;
            int ch = cc * 16 + col;
            float val = 0.f;
            if (col < 16) {
                int f = ch / 17, jt = ch % 17;
                int p = c_part_of[jt], j = c_idx_of[jt], ln = c_len_of[p];
                int ci = f * ln + j;
                for (int k = 0; k < 5; k++)
                    for (int v = 0; v < 6; v++) {
                        int dp = p - v + 1;
                        if (dp >= 0 && dp < 3)
                            val += A2[(k * 6 + v) * 6 + w] *
                                   w2[(((k * 16 + c) * 64 + ci) * 9 + dt) * 3 + dp];
                    }
                val *= s;
            }
            g_W2h[((it * 6 + mt) * 16 + row) * 24 + col] =
                __half_as_ushort(__float2half_rn(val));
        }
        if (threadIdx.x == 0) {
            float bias = 0.f;
            for (int k = 0; k < 5; k++) {
                float sa = 0.f;
                for (int v = 0; v < 6; v++) sa += A2[(k * 6 + v) * 6 + w];
                bias += b2[k * 16 + c] * sa;
            }
            g_B2[cw] = (bias - m2[cw]) * s + be2[cw];
        }
    } else if (bid < 625) {
        // W4 fp16 tiles + B3 + B4
        for (int e = threadIdx.x; e < 12 * 384; e += 256) {
            int ti = e / 384, rem = e - ti * 384;
            int o = rem / 24, col = rem % 24;
            int dk = ti >> 2, mt = ti & 3;
            float val = 0.f;
            if (col < 16) {
                int og = mt * 16 + o;
                val = w4[og * 48 + col * 3 + dk] * (g4[og] * rsqrtf(v4[og] + EPSV));
            }
            g_W4f[(ti * 16 + o) * 24 + col] = __half_as_ushort(__float2half_rn(val));
        }
        if (threadIdx.x < 16) {
            int o = threadIdx.x;
            float s = g3[o] * rsqrtf(v3[o] + EPSV);
            g_B3[o] = (b3[o] - m3[o]) * s + be3[o];
        }
        if (threadIdx.x >= 32 && threadIdx.x < 96) {
            int o = threadIdx.x - 32;
            float s = g4[o] * rsqrtf(v4[o] + EPSV);
            g_B4[o] = (b4[o] - m4[o]) * s + be4[o];
        }
    } else {
        // W3 fp16 tiles: 30 chunks x [16][24]
        int half = bid - 625;  // 0,1
        for (int e = half * 5760 + threadIdx.x; e < half * 5760 + 5760; e += 256) {
            int ck = e / 384, rem = e - ck * 384;
            int o = rem / 24, col = rem % 24;
            int cc = ck / 5, dt = ck % 5;
            float val = 0.f;
            if (col < 16) {
                float s = g3[o] * rsqrtf(v3[o] + EPSV);
                val = w3[o * 480 + (cc * 16 + col) * 5 + dt] * s;
            }
            g_W3t[(ck * 16 + o) * 24 + col] = __half_as_ushort(__float2half_rn(val));
        }
    }
}

// ---------------- stage 1 tensor GEMM (fp16 2-term; f1 stored single fp16) ----------------
#define K1_XOFF 7680
#define K1_XSZ  38016
__global__ void __launch_bounds__(256, 2) k1() {
    extern __shared__ char sm[];
    const int n = blockIdx.y, t0 = blockIdx.x * 256;
    const int z = blockIdx.z;
    const int mt0 = (z == 0) ? 0 : 1 + z * 4;
    const int mcount = (z == 0) ? 5 : 4;
    const int tid = threadIdx.x, lane = tid & 31, w = tid >> 5;
    char* Xh = sm + K1_XOFF;
    char* Xl = sm + K1_XOFF + K1_XSZ;

    auto prefW = [&](int it, char* buf) {
        const char* srcH = (const char*)(g_W1h + (size_t)(it * 17 + mt0) * 384);
        int cnt = mcount * 48;
        for (int i = tid; i < cnt; i += 256) cpa16(buf + i * 16, srcH + i * 16);
    };
    for (int i = tid; i < 264 * 8; i += 256) {
        int row = i >> 3, q = i & 7;
        int t = t0 - 4 + row;
        bool valid = (t >= 0 && t < 2048);
        size_t so = ((size_t)n * 2048 + (valid ? t : 0)) * 64 + q * 8;
        cpa16z(Xh + row * 144 + q * 16, g_Ph + so, valid);
        cpa16z(Xl + row * 144 + q * 16, g_Pl + so, valid);
    }
    prefW(0, sm); CP_COMMIT();

    float C[5][4][4];
#pragma unroll
    for (int i = 0; i < 5; i++)
#pragma unroll
        for (int j = 0; j < 4; j++)
#pragma unroll
            for (int q = 0; q < 4; q++) C[i][j][q] = 0.f;
    const int lrow = (lane & 15) * 48 + (lane >> 4) * 16;

    for (int it = 0; it < 36; it++) {
        char* buf = sm + (it & 1) * 3840;
        CP_WAIT0();
        __syncthreads();
        if (it + 1 < 36) { prefW(it + 1, sm + ((it + 1) & 1) * 3840); CP_COMMIT(); }
        const int dt = it >> 2, rc = it & 3;
        const int colb = (rc * 16 + (lane & 3) * 2) * 2;
        unsigned bh[4][2], bl[4][2];
#pragma unroll
        for (int nb = 0; nb < 4; nb++) {
            int tt = w * 32 + nb * 8 + (lane >> 2) + dt;
            const char* ph = Xh + tt * 144 + colb;
            const char* pl = Xl + tt * 144 + colb;
            bh[nb][0] = *(const unsigned*)ph; bh[nb][1] = *(const unsigned*)(ph + 16);
            bl[nb][0] = *(const unsigned*)pl; bl[nb][1] = *(const unsigned*)(pl + 16);
        }
        for (int mi = 0; mi < mcount; mi++) {
            unsigned Ah[4];
            ldsm4(Ah, buf + mi * 768 + lrow);
#pragma unroll
            for (int nb = 0; nb < 4; nb++) {
                mma_fp16(C[mi][nb], Ah, bh[nb][0], bh[nb][1]);
                mma_fp16(C[mi][nb], Ah, bl[nb][0], bl[nb][1]);
            }
        }
    }
    for (int mi = 0; mi < mcount; mi++) {
#pragma unroll
        for (int nb = 0; nb < 4; nb++) {
            int ch0 = (mt0 + mi) * 16 + (lane >> 2);
            int tt = t0 + w * 32 + nb * 8 + (lane & 3) * 2;
            float b0 = g_B1[ch0], b1 = g_B1[ch0 + 8];
            unsigned h0 = __half_as_ushort(__float2half_rn(C[mi][nb][0] + b0));
            unsigned h1 = __half_as_ushort(__float2half_rn(C[mi][nb][1] + b0));
            *(unsigned*)&g_f1h[((size_t)n * 272 + ch0) * 2048 + tt] = h0 | (h1 << 16);
            h0 = __half_as_ushort(__float2half_rn(C[mi][nb][2] + b1));
            h1 = __half_as_ushort(__float2half_rn(C[mi][nb][3] + b1));
            *(unsigned*)&g_f1h[((size_t)n * 272 + ch0 + 8) * 2048 + tt] = h0 | (h1 << 16);
        }
    }
}

// ---------------- stage 2 tensor GEMM (fp16 1-term, K-split over z) ----------------
#define K2_WSZ 9216
#define K2_XB  12672
__global__ void __launch_bounds__(256, 2) k2() {
    extern __shared__ char sm[];
    const int n = blockIdx.y, t0 = blockIdx.x * 256;
    const int zz = blockIdx.z;
    const int cc0 = zz ? 9 : 0;
    const int ncc = zz ? 8 : 9;
    const int tid = threadIdx.x, lane = tid & 31, w = tid >> 5;
    const int g = tid & 15, jj = tid >> 4;
    unsigned sh[9];

    auto prefW = [&](int it, char* buf) {
        const char* srcH = (const char*)(g_W2h + (size_t)it * 2304);
        for (int i = tid; i < 288; i += 256) cpa16(buf + i * 16, srcH + i * 16);
    };
    auto loadX = [&](int cc) {
        size_t base = ((size_t)n * 272 + cc * 16 + g) * 2048;
#pragma unroll
        for (int i = 0; i < 9; i++) {
            int p = jj + 16 * i;
            sh[i] = 0;
            if (p < 132) {
                int t = t0 - 4 + 2 * p;
                if (t >= 0 && t < 2048) sh[i] = *(const unsigned*)(g_f1h + base + t);
            }
        }
    };
    auto stsX = [&](int buf) {
        unsigned short* Xh = (unsigned short*)(sm + K2_WSZ + buf * K2_XB);
#pragma unroll
        for (int i = 0; i < 9; i++) {
            int p = jj + 16 * i;
            if (p < 132) {
                Xh[(2 * p) * 24 + g] = (unsigned short)(sh[i] & 0xffff);
                Xh[(2 * p + 1) * 24 + g] = (unsigned short)(sh[i] >> 16);
            }
        }
    };

    loadX(cc0);
    stsX(0);
    prefW(cc0 * 9, sm);
    CP_COMMIT();

    float C[6][4][4];
#pragma unroll
    for (int i = 0; i < 6; i++)
#pragma unroll
        for (int j = 0; j < 4; j++)
#pragma unroll
            for (int q = 0; q < 4; q++) C[i][j][q] = 0.f;

    const int lrow = (lane & 15) * 48 + (lane >> 4) * 16;
    const int colb = ((lane & 3) * 2) * 2;
    const int nit = ncc * 9;

    for (int i = 0; i < nit; i++) {
        const int ccl = i / 9, dt = i - ccl * 9;
        char* buf = sm + (i & 1) * 4608;
        CP_WAIT0();
        __syncthreads();
        if (i + 1 < nit) { prefW(cc0 * 9 + i + 1, sm + ((i + 1) & 1) * 4608); CP_COMMIT(); }
        if (dt == 0 && ccl + 1 < ncc) loadX(cc0 + ccl + 1);
        if (dt == 7 && ccl + 1 < ncc) stsX((ccl + 1) & 1);

        const char* Xh = sm + K2_WSZ + (ccl & 1) * K2_XB;
        unsigned bh[4][2];
#pragma unroll
        for (int nb = 0; nb < 4; nb++) {
            int tt = w * 32 + nb * 8 + (lane >> 2) + dt;
            const char* ph = Xh + tt * 48 + colb;
            bh[nb][0] = *(const unsigned*)ph; bh[nb][1] = *(const unsigned*)(ph + 16);
        }
#pragma unroll
        for (int mi = 0; mi < 6; mi++) {
            unsigned Ah[4];
            ldsm4(Ah, buf + mi * 768 + lrow);
#pragma unroll
            for (int nb = 0; nb < 4; nb++)
                mma_fp16(C[mi][nb], Ah, bh[nb][0], bh[nb][1]);
        }
    }

    float* dst = zz ? g_f2b : g_f2;
#pragma unroll
    for (int mi = 0; mi < 6; mi++) {
#pragma unroll
        for (int nb = 0; nb < 4; nb++) {
            int ch0 = mi * 16 + (lane >> 2);
            int tt = t0 + w * 32 + nb * 8 + (lane & 3) * 2;
            float b0 = zz ? 0.f : g_B2[ch0];
            float b1 = zz ? 0.f : g_B2[ch0 + 8];
            float2 v0 = make_float2(C[mi][nb][0] + b0, C[mi][nb][1] + b0);
            float2 v1 = make_float2(C[mi][nb][2] + b1, C[mi][nb][3] + b1);
            *(float2*)&dst[((size_t)n * 96 + ch0) * 2048 + tt] = v0;
            *(float2*)&dst[((size_t)n * 96 + ch0 + 8) * 2048 + tt] = v1;
        }
    }
}

// ---------------- stages 3+4: both tensorized ----------------
// smem: Xh 29952 | Xl 29952 | Wt3 23040 | W4f 9216 | F3h 6336 | F3l 6336 = 104832
#define S_XL   29952
#define S_WT3  59904
#define S_W4F  82944
#define S_F3H  92160
#define S_F3L  98496
__global__ void __launch_bounds__(256, 2) k34(float* __restrict__ out) {
    extern __shared__ char smc[];
    unsigned short* Xh = (unsigned short*)smc;
    unsigned short* Xl = (unsigned short*)(smc + S_XL);
    char* Wt = smc + S_WT3;
    char* W4 = smc + S_W4F;
    unsigned short* F3h = (unsigned short*)(smc + S_F3H);
    unsigned short* F3l = (unsigned short*)(smc + S_F3L);
    const int n = blockIdx.y;
    const int t0 = blockIdx.x * 128;
    const int tid = threadIdx.x, lane = tid & 31, w = tid >> 5;

    for (int i = tid; i < 1440; i += 256) cpa16(Wt + i * 16, (const char*)g_W3t + i * 16);
    for (int i = tid; i < 576; i += 256) cpa16(W4 + i * 16, (const char*)g_W4f + i * 16);
    CP_COMMIT();

    for (int idx = tid; idx < 96 * 144; idx += 256) {
        int ch = idx / 144, xr = idx - ch * 144;
        int t = t0 - 4 + xr;
        float v = 0.f;
        if (t >= 0 && t < 2048) {
            size_t o = ((size_t)n * 96 + ch) * 2048 + t;
            v = g_f2[o] + g_f2b[o];
        }
        unsigned short h, l; split_fp16(v, h, l);
        Xh[xr * 104 + ch] = h; Xl[xr * 104 + ch] = l;
    }
    CP_WAIT0();
    __syncthreads();

    // ---- f3 GEMM (M=16, K=480, 2-term X) ----
    float C[3][4];
#pragma unroll
    for (int q = 0; q < 3; q++)
#pragma unroll
        for (int j = 0; j < 4; j++) C[q][j] = 0.f;
    const int nnb = (w == 0) ? 3 : 2;
    int nbs[3]; nbs[0] = w; nbs[1] = 8 + w; nbs[2] = 16;
    const int lrow = (lane & 15) * 48 + (lane >> 4) * 16;

    for (int ck = 0; ck < 30; ck++) {
        const int cc = ck / 5, dt = ck % 5;
        unsigned A[4];
        ldsm4(A, Wt + ck * 768 + lrow);
#pragma unroll
        for (int q = 0; q < 3; q++) {
            if (q >= nnb) break;
            int xr = nbs[q] * 8 + (lane >> 2) + dt + 1;
            const char* ph = (const char*)Xh + xr * 208 + cc * 32 + (lane & 3) * 4;
            const char* pl = (const char*)Xl + xr * 208 + cc * 32 + (lane & 3) * 4;
            mma_fp16(C[q], A, *(const unsigned*)ph, *(const unsigned*)(ph + 16));
            mma_fp16(C[q], A, *(const unsigned*)pl, *(const unsigned*)(pl + 16));
        }
    }
    {   // f3 epilogue: bias + leaky -> split fp16 F3h/F3l [s:132][24 ushort stride]
        int o0 = lane >> 2;
        float bb0 = __ldg(&g_B3[o0]), bb1 = __ldg(&g_B3[o0 + 8]);
#pragma unroll
        for (int q = 0; q < 3; q++) {
            if (q >= nnb) break;
            int s0 = nbs[q] * 8 + (lane & 3) * 2;
#pragma unroll
            for (int j = 0; j < 2; j++) {
                int s = s0 + j;
                if (s < 132) {
                    int t3 = t0 - 1 + s;
                    bool ok = (t3 >= 0 && t3 < 2048);
                    float a = C[q][j] + bb0;
                    float b = C[q][2 + j] + bb1;
                    float va = ok ? (a > 0.f ? a : 0.01f * a) : 0.f;
                    float vb = ok ? (b > 0.f ? b : 0.01f * b) : 0.f;
                    unsigned short h, l;
                    split_fp16(va, h, l);
                    F3h[s * 24 + o0] = h; F3l[s * 24 + o0] = l;
                    split_fp16(vb, h, l);
                    F3h[s * 24 + o0 + 8] = h; F3l[s * 24 + o0 + 8] = l;
                }
            }
        }
    }
    __syncthreads();

    // ---- f4 GEMM (M=64, K=48, fp16 W4 single-term, F3 2-term) ----
    float C4[4][2][4];
#pragma unroll
    for (int mt = 0; mt < 4; mt++)
#pragma unroll
        for (int nb = 0; nb < 2; nb++)
#pragma unroll
            for (int j = 0; j < 4; j++) C4[mt][nb][j] = 0.f;

    for (int dk = 0; dk < 3; dk++) {
        unsigned bh[2][2], bl[2][2];
#pragma unroll
        for (int nb = 0; nb < 2; nb++) {
            int row = w * 16 + nb * 8 + (lane >> 2) + dk;
            const char* ph = (const char*)F3h + row * 48 + (lane & 3) * 4;
            const char* pl = (const char*)F3l + row * 48 + (lane & 3) * 4;
            bh[nb][0] = *(const unsigned*)ph; bh[nb][1] = *(const unsigned*)(ph + 16);
            bl[nb][0] = *(const unsigned*)pl; bl[nb][1] = *(const unsigned*)(pl + 16);
        }
#pragma unroll
        for (int mt = 0; mt < 4; mt++) {
            unsigned A[4];
            ldsm4(A, W4 + (dk * 4 + mt) * 768 + lrow);
#pragma unroll
            for (int nb = 0; nb < 2; nb++) {
                mma_fp16(C4[mt][nb], A, bh[nb][0], bh[nb][1]);
                mma_fp16(C4[mt][nb], A, bl[nb][0], bl[nb][1]);
            }
        }
    }
    // f4 epilogue
#pragma unroll
    for (int mt = 0; mt < 4; mt++) {
        int o = mt * 16 + (lane >> 2);
        float b0 = __ldg(&g_B4[o]), b1 = __ldg(&g_B4[o + 8]);
#pragma unroll
        for (int nb = 0; nb < 2; nb++) {
            int t = t0 + w * 16 + nb * 8 + (lane & 3) * 2;
            float* po = &out[((size_t)n * 2048 + t) * 64];
            float a0 = C4[mt][nb][0] + b0, a1 = C4[mt][nb][1] + b0;
            float a2 = C4[mt][nb][2] + b1, a3 = C4[mt][nb][3] + b1;
            po[o] = a0 > 0.f ? a0 : 0.01f * a0;
            po[64 + o] = a1 > 0.f ? a1 : 0.01f * a1;
            po[o + 8] = a2 > 0.f ? a2 : 0.01f * a2;
            po[64 + o + 8] = a3 > 0.f ? a3 : 0.01f * a3;
        }
    }
}

// ---------------- launch ----------------
extern "C" void kernel_launch(void* const* d_in, const int* in_sizes, int n_in,
                              void* d_out, int out_size) {
    (void)in_sizes; (void)n_in; (void)out_size;
    const float* poses = (const float*)d_in[0];
    const float* A1 = (const float*)d_in[1];
    const float* A2 = (const float*)d_in[2];
    const float* w1 = (const float*)d_in[3];
    const float* b1 = (const float*)d_in[4];
    const float* g1 = (const float*)d_in[5];
    const float* be1 = (const float*)d_in[6];
    const float* m1 = (const float*)d_in[7];
    const float* v1 = (const float*)d_in[8];
    const float* w2 = (const float*)d_in[9];
    const float* b2 = (const float*)d_in[10];
    const float* g2 = (const float*)d_in[11];
    const float* be2 = (const float*)d_in[12];
    const float* m2 = (const float*)d_in[13];
    const float* v2 = (const float*)d_in[14];
    const float* w3 = (const float*)d_in[15];
    const float* b3 = (const float*)d_in[16];
    const float* g3 = (const float*)d_in[17];
    const float* be3 = (const float*)d_in[18];
    const float* m3 = (const float*)d_in[19];
    const float* v3 = (const float*)d_in[20];
    const float* w4 = (const float*)d_in[21];
    const float* b4 = (const float*)d_in[22];
    const float* g4 = (const float*)d_in[23];
    const float* be4 = (const float*)d_in[24];
    const float* m4 = (const float*)d_in[25];
    const float* v4 = (const float*)d_in[26];
    float* out = (float*)d_out;

    size_t sm1 = 83712;
    size_t sm2 = K2_WSZ + 2 * K2_XB;   // 34560
    size_t sm34 = 104832;
    cudaFuncSetAttribute(k1, cudaFuncAttributeMaxDynamicSharedMemorySize, (int)sm1);
    cudaFuncSetAttribute(k2, cudaFuncAttributeMaxDynamicSharedMemorySize, (int)sm2);
    cudaFuncSetAttribute(k34, cudaFuncAttributeMaxDynamicSharedMemorySize, (int)sm34);

    prepAll<<<627, 256>>>(poses,
                          A1, w1, b1, g1, be1, m1, v1,
                          A2, w2, b2, g2, be2, m2, v2,
                          w3, b3, g3, be3, m3, v3,
                          w4, b4, g4, be4, m4, v4);
    k1<<<dim3(8, 16, 4), 256, sm1>>>();
    k2<<<dim3(8, 16, 2), 256, sm2>>>();
    k34<<<dim3(16, 16), 256, sm34>>>(out);
}

// round 14
// speedup vs baseline: 1.6741x; 1.6741x over previous
#include <cuda_runtime.h>
#include <cuda_fp16.h>

#define EPSV 1e-5f

// ---------------- device scratch ----------------
__device__ __align__(16) unsigned short g_W1h[36 * 17 * 16 * 24];   // fp16
__device__ __align__(16) unsigned short g_W2h[153 * 6 * 16 * 24];   // fp16
__device__ __align__(16) unsigned short g_W3t[30 * 16 * 24];        // fp16 f3 tiles
__device__ __align__(16) unsigned short g_W4f[12 * 16 * 24];        // fp16 f4 tiles
__device__ float g_B1[272];
__device__ float g_B2[96];
__device__ float g_B3[16];
__device__ float g_B4[64];
__device__ __align__(16) unsigned short g_Ph[16 * 2048 * 64];
__device__ __align__(16) unsigned short g_Pl[16 * 2048 * 64];
__device__ __align__(16) unsigned short g_f1t[16 * 2048 * 288];     // f1 fp16 TRANSPOSED [n][t][ch,pad]
__device__ float g_f2[16 * 96 * 2048];
__device__ float g_f2b[16 * 96 * 2048];

__constant__ int c_part_of[17] = {1,2,3,1,1,4,4,5,5,2,2,3,3,0,0,0,0};
__constant__ int c_idx_of[17]  = {0,0,0,1,2,0,1,0,1,1,2,1,2,0,1,2,3};
__constant__ int c_len_of[6]   = {4,3,3,3,2,2};

// ---------------- helpers ----------------
__device__ __forceinline__ void split_fp16(float x, unsigned short& h, unsigned short& l) {
    __half hh = __float2half_rn(x);
    float r = x - __half2float(hh);
    __half ll = __float2half_rn(r);
    h = __half_as_ushort(hh); l = __half_as_ushort(ll);
}
__device__ __forceinline__ void ldsm4(unsigned r[4], const void* p) {
    unsigned a = (unsigned)__cvta_generic_to_shared(p);
    asm volatile("ldmatrix.sync.aligned.m8n8.x4.shared.b16 {%0,%1,%2,%3},[%4];"
                 : "=r"(r[0]), "=r"(r[1]), "=r"(r[2]), "=r"(r[3]) : "r"(a));
}
__device__ __forceinline__ void mma_fp16(float* c, const unsigned* a, unsigned b0, unsigned b1) {
    asm volatile("mma.sync.aligned.m16n8k16.row.col.f32.f16.f16.f32 "
                 "{%0,%1,%2,%3},{%4,%5,%6,%7},{%8,%9},{%0,%1,%2,%3};"
                 : "+f"(c[0]), "+f"(c[1]), "+f"(c[2]), "+f"(c[3])
                 : "r"(a[0]), "r"(a[1]), "r"(a[2]), "r"(a[3]), "r"(b0), "r"(b1));
}
__device__ __forceinline__ void cpa16(void* dst, const void* src) {
    unsigned d = (unsigned)__cvta_generic_to_shared(dst);
    asm volatile("cp.async.cg.shared.global [%0], [%1], 16;" :: "r"(d), "l"(src));
}
__device__ __forceinline__ void cpa16z(void* dst, const void* src, bool valid) {
    unsigned d = (unsigned)__cvta_generic_to_shared(dst);
    int sz = valid ? 16 : 0;
    asm volatile("cp.async.cg.shared.global [%0], [%1], 16, %2;" :: "r"(d), "l"(src), "r"(sz));
}
#define CP_COMMIT() asm volatile("cp.async.commit_group;")
#define CP_WAIT0()  asm volatile("cp.async.wait_group 0;")

// ---------------- fused prep (627 blocks x 256 thr) ----------------
__global__ void prepAll(const float* __restrict__ poses,
                        const float* __restrict__ A1, const float* __restrict__ w1,
                        const float* __restrict__ b1, const float* __restrict__ g1,
                        const float* __restrict__ be1, const float* __restrict__ m1,
                        const float* __restrict__ v1,
                        const float* __restrict__ A2, const float* __restrict__ w2,
                        const float* __restrict__ b2, const float* __restrict__ g2,
                        const float* __restrict__ be2, const float* __restrict__ m2,
                        const float* __restrict__ v2,
                        const float* __restrict__ w3, const float* __restrict__ b3,
                        const float* __restrict__ g3, const float* __restrict__ be3,
                        const float* __restrict__ m3, const float* __restrict__ v3,
                        const float* __restrict__ w4, const float* __restrict__ b4,
                        const float* __restrict__ g4, const float* __restrict__ be4,
                        const float* __restrict__ m4, const float* __restrict__ v4) {
    const int bid = blockIdx.x;
    if (bid < 256) {
        const int n = bid >> 4, tb = (bid & 15) * 128;
        for (int idx = threadIdx.x; idx < 128 * 64; idx += 256) {
            int tl = idx >> 6, col = idx & 63;
            int t = tb + tl;
            float v = (col < 51) ? poses[((size_t)n * 2048 + t) * 51 + col] : 0.f;
            unsigned short h, l; split_fp16(v, h, l);
            size_t o = ((size_t)n * 2048 + t) * 64 + col;
            g_Ph[o] = h; g_Pl[o] = l;
        }
    } else if (bid < 528) {
        int cw = bid - 256;
        int c = cw / 17, w = cw % 17;
        int mt = cw >> 4, row = cw & 15;
        float s = g1[cw] * rsqrtf(v1[cw] + EPSV);
        for (int e = threadIdx.x; e < 36 * 24; e += 256) {
            int it = e / 24, col = e % 24;
            int dt = it >> 2, rc = it & 3;
            int r = rc * 16 + col;
            float val = 0.f;
            if (col < 16 && r < 51) {
                int u = r / 3, ci = r % 3;
                for (int k = 0; k < 5; k++)
                    for (int dv = 0; dv < 5; dv++) {
                        int v = u - dv + 2;
                        if (v >= 0 && v < 17)
                            val += A1[(k * 17 + v) * 17 + w] *
                                   w1[(((k * 16 + c) * 3 + ci) * 9 + dt) * 5 + dv];
                    }
                val *= s;
            }
            g_W1h[((it * 17 + mt) * 16 + row) * 24 + col] =
                __half_as_ushort(__float2half_rn(val));
        }
        if (threadIdx.x == 0) {
            float bias = 0.f;
            for (int k = 0; k < 5; k++) {
                float sa = 0.f;
                for (int v = 0; v < 17; v++) sa += A1[(k * 17 + v) * 17 + w];
                bias += b1[k * 16 + c] * sa;
            }
            g_B1[cw] = (bias - m1[cw]) * s + be1[cw];
        }
    } else if (bid < 624) {
        int cw = bid - 528;
        int c = cw / 6, w = cw % 6;
        int mt = cw >> 4, row = cw & 15;
        float s = g2[cw] * rsqrtf(v2[cw] + EPSV);
        for (int e = threadIdx.x; e < 153 * 24; e += 256) {
            int it = e / 24, col = e % 24;
            int cc = it / 9, dt = it % 9;
            int ch = cc * 16 + col;
            float val = 0.f;
            if (col < 16) {
                int f = ch / 17, jt = ch % 17;
                int p = c_part_of[jt], j = c_idx_of[jt], ln = c_len_of[p];
                int ci = f * ln + j;
                for (int k = 0; k < 5; k++)
                    for (int v = 0; v < 6; v++) {
                        int dp = p - v + 1;
                        if (dp >= 0 && dp < 3)
                            val += A2[(k * 6 + v) * 6 + w] *
                                   w2[(((k * 16 + c) * 64 + ci) * 9 + dt) * 3 + dp];
                    }
                val *= s;
            }
            g_W2h[((it * 6 + mt) * 16 + row) * 24 + col] =
                __half_as_ushort(__float2half_rn(val));
        }
        if (threadIdx.x == 0) {
            float bias = 0.f;
            for (int k = 0; k < 5; k++) {
                float sa = 0.f;
                for (int v = 0; v < 6; v++) sa += A2[(k * 6 + v) * 6 + w];
                bias += b2[k * 16 + c] * sa;
            }
            g_B2[cw] = (bias - m2[cw]) * s + be2[cw];
        }
    } else if (bid < 625) {
        for (int e = threadIdx.x; e < 12 * 384; e += 256) {
            int ti = e / 384, rem = e - ti * 384;
            int o = rem / 24, col = rem % 24;
            int dk = ti >> 2, mt = ti & 3;
            float val = 0.f;
            if (col < 16) {
                int og = mt * 16 + o;
                val = w4[og * 48 + col * 3 + dk] * (g4[og] * rsqrtf(v4[og] + EPSV));
            }
            g_W4f[(ti * 16 + o) * 24 + col] = __half_as_ushort(__float2half_rn(val));
        }
        if (threadIdx.x < 16) {
            int o = threadIdx.x;
            float s = g3[o] * rsqrtf(v3[o] + EPSV);
            g_B3[o] = (b3[o] - m3[o]) * s + be3[o];
        }
        if (threadIdx.x >= 32 && threadIdx.x < 96) {
            int o = threadIdx.x - 32;
            float s = g4[o] * rsqrtf(v4[o] + EPSV);
            g_B4[o] = (b4[o] - m4[o]) * s + be4[o];
        }
    } else {
        int half = bid - 625;  // 0,1
        for (int e = half * 5760 + threadIdx.x; e < half * 5760 + 5760; e += 256) {
            int ck = e / 384, rem = e - ck * 384;
            int o = rem / 24, col = rem % 24;
            int cc = ck / 5, dt = ck % 5;
            float val = 0.f;
            if (col < 16) {
                float s = g3[o] * rsqrtf(v3[o] + EPSV);
                val = w3[o * 480 + (cc * 16 + col) * 5 + dt] * s;
            }
            g_W3t[(ck * 16 + o) * 24 + col] = __half_as_ushort(__float2half_rn(val));
        }
    }
}

// ---------------- stage 1 tensor GEMM (fp16 2-term; transposed fp16 output) ----------------
#define K1_XOFF 7680
#define K1_XSZ  38016
__global__ void __launch_bounds__(256, 2) k1() {
    extern __shared__ char sm[];
    const int n = blockIdx.y, t0 = blockIdx.x * 256;
    const int z = blockIdx.z;
    const int mt0 = (z == 0) ? 0 : 1 + z * 4;
    const int mcount = (z == 0) ? 5 : 4;
    const int tid = threadIdx.x, lane = tid & 31, w = tid >> 5;
    char* Xh = sm + K1_XOFF;
    char* Xl = sm + K1_XOFF + K1_XSZ;

    auto prefW = [&](int it, char* buf) {
        const char* srcH = (const char*)(g_W1h + (size_t)(it * 17 + mt0) * 384);
        int cnt = mcount * 48;
        for (int i = tid; i < cnt; i += 256) cpa16(buf + i * 16, srcH + i * 16);
    };
    for (int i = tid; i < 264 * 8; i += 256) {
        int row = i >> 3, q = i & 7;
        int t = t0 - 4 + row;
        bool valid = (t >= 0 && t < 2048);
        size_t so = ((size_t)n * 2048 + (valid ? t : 0)) * 64 + q * 8;
        cpa16z(Xh + row * 144 + q * 16, g_Ph + so, valid);
        cpa16z(Xl + row * 144 + q * 16, g_Pl + so, valid);
    }
    prefW(0, sm); CP_COMMIT();

    float C[5][4][4];
#pragma unroll
    for (int i = 0; i < 5; i++)
#pragma unroll
        for (int j = 0; j < 4; j++)
#pragma unroll
            for (int q = 0; q < 4; q++) C[i][j][q] = 0.f;
    const int lrow = (lane & 15) * 48 + (lane >> 4) * 16;

    for (int it = 0; it < 36; it++) {
        char* buf = sm + (it & 1) * 3840;
        CP_WAIT0();
        __syncthreads();
        if (it + 1 < 36) { prefW(it + 1, sm + ((it + 1) & 1) * 3840); CP_COMMIT(); }
        const int dt = it >> 2, rc = it & 3;
        const int colb = (rc * 16 + (lane & 3) * 2) * 2;
        unsigned bh[4][2], bl[4][2];
#pragma unroll
        for (int nb = 0; nb < 4; nb++) {
            int tt = w * 32 + nb * 8 + (lane >> 2) + dt;
            const char* ph = Xh + tt * 144 + colb;
            const char* pl = Xl + tt * 144 + colb;
            bh[nb][0] = *(const unsigned*)ph; bh[nb][1] = *(const unsigned*)(ph + 16);
            bl[nb][0] = *(const unsigned*)pl; bl[nb][1] = *(const unsigned*)(pl + 16);
        }
        for (int mi = 0; mi < mcount; mi++) {
            unsigned Ah[4];
            ldsm4(Ah, buf + mi * 768 + lrow);
#pragma unroll
            for (int nb = 0; nb < 4; nb++) {
                mma_fp16(C[mi][nb], Ah, bh[nb][0], bh[nb][1]);
                mma_fp16(C[mi][nb], Ah, bl[nb][0], bl[nb][1]);
            }
        }
    }

    // epilogue: stage transposed [t][ch] fp16 tile in smem, then coalesced STG.128
    __syncthreads();
    unsigned short* T = (unsigned short*)(sm + K1_XOFF);   // [256][88]
    for (int mi = 0; mi < mcount; mi++) {
        int chl = mi * 16 + (lane >> 2);
        float b0 = g_B1[mt0 * 16 + chl], b1 = g_B1[mt0 * 16 + chl + 8];
#pragma unroll
        for (int nb = 0; nb < 4; nb++) {
            int tl = w * 32 + nb * 8 + (lane & 3) * 2;
            T[tl * 88 + chl]           = __half_as_ushort(__float2half_rn(C[mi][nb][0] + b0));
            T[(tl + 1) * 88 + chl]     = __half_as_ushort(__float2half_rn(C[mi][nb][1] + b0));
            T[tl * 88 + chl + 8]       = __half_as_ushort(__float2half_rn(C[mi][nb][2] + b1));
            T[(tl + 1) * 88 + chl + 8] = __half_as_ushort(__float2half_rn(C[mi][nb][3] + b1));
        }
    }
    __syncthreads();
    const int ncp = mcount * 2;   // 16B chunks per row
    for (int idx = tid; idx < 256 * ncp; idx += 256) {
        int row = idx / ncp, cp = idx - row * ncp;
        uint4 v = *(const uint4*)(T + row * 88 + cp * 8);
        *(uint4*)&g_f1t[((size_t)n * 2048 + t0 + row) * 288 + mt0 * 16 + cp * 8] = v;
    }
}

// ---------------- stage 2 tensor GEMM (fp16 1-term, cp.async X, K-split over z) ----------------
#define K2_WSZ 9216
#define K2_XB  12672
__global__ void __launch_bounds__(256, 2) k2() {
    extern __shared__ char sm[];
    const int n = blockIdx.y, t0 = blockIdx.x * 256;
    const int zz = blockIdx.z;
    const int cc0 = zz ? 9 : 0;
    const int ncc = zz ? 8 : 9;
    const int tid = threadIdx.x, lane = tid & 31, w = tid >> 5;

    auto prefW = [&](int it, char* buf) {
        const char* srcH = (const char*)(g_W2h + (size_t)it * 2304);
        for (int i = tid; i < 288; i += 256) cpa16(buf + i * 16, srcH + i * 16);
    };
    auto prefX = [&](int cc, int buf) {
        char* dst = sm + K2_WSZ + buf * K2_XB;
        for (int r = tid; r < 264; r += 256) {
            int t = t0 - 4 + r;
            bool valid = (t >= 0 && t < 2048);
            const unsigned short* src =
                g_f1t + ((size_t)n * 2048 + (valid ? t : 0)) * 288 + cc * 16;
            cpa16z(dst + r * 48, src, valid);
            cpa16z(dst + r * 48 + 16, src + 8, valid);
        }
    };

    prefX(cc0, 0);
    prefW(cc0 * 9, sm);
    CP_COMMIT();

    float C[6][4][4];
#pragma unroll
    for (int i = 0; i < 6; i++)
#pragma unroll
        for (int j = 0; j < 4; j++)
#pragma unroll
            for (int q = 0; q < 4; q++) C[i][j][q] = 0.f;

    const int lrow = (lane & 15) * 48 + (lane >> 4) * 16;
    const int colb = (lane & 3) * 4;
    const int nit = ncc * 9;

    for (int i = 0; i < nit; i++) {
        const int ccl = i / 9, dt = i - ccl * 9;
        char* buf = sm + (i & 1) * 4608;
        CP_WAIT0();
        __syncthreads();
        if (i + 1 < nit) { prefW(cc0 * 9 + i + 1, sm + ((i + 1) & 1) * 4608); }
        if (dt == 0 && ccl + 1 < ncc) prefX(cc0 + ccl + 1, (ccl + 1) & 1);
        if (i + 1 < nit) CP_COMMIT();

        const char* Xb = sm + K2_WSZ + (ccl & 1) * K2_XB;
        unsigned bh[4][2];
#pragma unroll
        for (int nb = 0; nb < 4; nb++) {
            int tt = w * 32 + nb * 8 + (lane >> 2) + dt;
            const char* ph = Xb + tt * 48 + colb;
            bh[nb][0] = *(const unsigned*)ph; bh[nb][1] = *(const unsigned*)(ph + 16);
        }
#pragma unroll
        for (int mi = 0; mi < 6; mi++) {
            unsigned Ah[4];
            ldsm4(Ah, buf + mi * 768 + lrow);
#pragma unroll
            for (int nb = 0; nb < 4; nb++)
                mma_fp16(C[mi][nb], Ah, bh[nb][0], bh[nb][1]);
        }
    }

    float* dst = zz ? g_f2b : g_f2;
#pragma unroll
    for (int mi = 0; mi < 6; mi++) {
#pragma unroll
        for (int nb = 0; nb < 4; nb++) {
            int ch0 = mi * 16 + (lane >> 2);
            int tt = t0 + w * 32 + nb * 8 + (lane & 3) * 2;
            float b0 = zz ? 0.f : g_B2[ch0];
            float b1 = zz ? 0.f : g_B2[ch0 + 8];
            float2 v0 = make_float2(C[mi][nb][0] + b0, C[mi][nb][1] + b0);
            float2 v1 = make_float2(C[mi][nb][2] + b1, C[mi][nb][3] + b1);
            *(float2*)&dst[((size_t)n * 96 + ch0) * 2048 + tt] = v0;
            *(float2*)&dst[((size_t)n * 96 + ch0 + 8) * 2048 + tt] = v1;
        }
    }
}

// ---------------- stages 3+4: both tensorized ----------------
#define S_XL   29952
#define S_WT3  59904
#define S_W4F  82944
#define S_F3H  92160
#define S_F3L  98496
__global__ void __launch_bounds__(256, 2) k34(float* __restrict__ out) {
    extern __shared__ char smc[];
    unsigned short* Xh = (unsigned short*)smc;
    unsigned short* Xl = (unsigned short*)(smc + S_XL);
    char* Wt = smc + S_WT3;
    char* W4 = smc + S_W4F;
    unsigned short* F3h = (unsigned short*)(smc + S_F3H);
    unsigned short* F3l = (unsigned short*)(smc + S_F3L);
    const int n = blockIdx.y;
    const int t0 = blockIdx.x * 128;
    const int tid = threadIdx.x, lane = tid & 31, w = tid >> 5;

    for (int i = tid; i < 1440; i += 256) cpa16(Wt + i * 16, (const char*)g_W3t + i * 16);
    for (int i = tid; i < 576; i += 256) cpa16(W4 + i * 16, (const char*)g_W4f + i * 16);
    CP_COMMIT();

    for (int idx = tid; idx < 96 * 144; idx += 256) {
        int ch = idx / 144, xr = idx - ch * 144;
        int t = t0 - 4 + xr;
        float v = 0.f;
        if (t >= 0 && t < 2048) {
            size_t o = ((size_t)n * 96 + ch) * 2048 + t;
            v = g_f2[o] + g_f2b[o];
        }
        unsigned short h, l; split_fp16(v, h, l);
        Xh[xr * 104 + ch] = h; Xl[xr * 104 + ch] = l;
    }
    CP_WAIT0();
    __syncthreads();

    // ---- f3 GEMM (M=16, K=480, 2-term X) ----
    float C[3][4];
#pragma unroll
    for (int q = 0; q < 3; q++)
#pragma unroll
        for (int j = 0; j < 4; j++) C[q][j] = 0.f;
    const int nnb = (w == 0) ? 3 : 2;
    int nbs[3]; nbs[0] = w; nbs[1] = 8 + w; nbs[2] = 16;
    const int lrow = (lane & 15) * 48 + (lane >> 4) * 16;

    for (int ck = 0; ck < 30; ck++) {
        const int cc = ck / 5, dt = ck % 5;
        unsigned A[4];
        ldsm4(A, Wt + ck * 768 + lrow);
#pragma unroll
        for (int q = 0; q < 3; q++) {
            if (q >= nnb) break;
            int xr = nbs[q] * 8 + (lane >> 2) + dt + 1;
            const char* ph = (const char*)Xh + xr * 208 + cc * 32 + (lane & 3) * 4;
            const char* pl = (const char*)Xl + xr * 208 + cc * 32 + (lane & 3) * 4;
            mma_fp16(C[q], A, *(const unsigned*)ph, *(const unsigned*)(ph + 16));
            mma_fp16(C[q], A, *(const unsigned*)pl, *(const unsigned*)(pl + 16));
        }
    }
    {   // f3 epilogue -> split fp16 F3h/F3l [s:132][24 stride]
        int o0 = lane >> 2;
        float bb0 = __ldg(&g_B3[o0]), bb1 = __ldg(&g_B3[o0 + 8]);
#pragma unroll
        for (int q = 0; q < 3; q++) {
            if (q >= nnb) break;
            int s0 = nbs[q] * 8 + (lane & 3) * 2;
#pragma unroll
            for (int j = 0; j < 2; j++) {
                int s = s0 + j;
                if (s < 132) {
                    int t3 = t0 - 1 + s;
                    bool ok = (t3 >= 0 && t3 < 2048);
                    float a = C[q][j] + bb0;
                    float b = C[q][2 + j] + bb1;
                    float va = ok ? (a > 0.f ? a : 0.01f * a) : 0.f;
                    float vb = ok ? (b > 0.f ? b : 0.01f * b) : 0.f;
                    unsigned short h, l;
                    split_fp16(va, h, l);
                    F3h[s * 24 + o0] = h; F3l[s * 24 + o0] = l;
                    split_fp16(vb, h, l);
                    F3h[s * 24 + o0 + 8] = h; F3l[s * 24 + o0 + 8] = l;
                }
            }
        }
    }
    __syncthreads();

    // ---- f4 GEMM (M=64, K=48) ----
    float C4[4][2][4];
#pragma unroll
    for (int mt = 0; mt < 4; mt++)
#pragma unroll
        for (int nb = 0; nb < 2; nb++)
#pragma unroll
            for (int j = 0; j < 4; j++) C4[mt][nb][j] = 0.f;

    for (int dk = 0; dk < 3; dk++) {
        unsigned bh[2][2], bl[2][2];
#pragma unroll
        for (int nb = 0; nb < 2; nb++) {
            int row = w * 16 + nb * 8 + (lane >> 2) + dk;
            const char* ph = (const char*)F3h + row * 48 + (lane & 3) * 4;
            const char* pl = (const char*)F3l + row * 48 + (lane & 3) * 4;
            bh[nb][0] = *(const unsigned*)ph; bh[nb][1] = *(const unsigned*)(ph + 16);
            bl[nb][0] = *(const unsigned*)pl; bl[nb][1] = *(const unsigned*)(pl + 16);
        }
#pragma unroll
        for (int mt = 0; mt < 4; mt++) {
            unsigned A[4];
            ldsm4(A, W4 + (dk * 4 + mt) * 768 + lrow);
#pragma unroll
            for (int nb = 0; nb < 2; nb++) {
                mma_fp16(C4[mt][nb], A, bh[nb][0], bh[nb][1]);
                mma_fp16(C4[mt][nb], A, bl[nb][0], bl[nb][1]);
            }
        }
    }
#pragma unroll
    for (int mt = 0; mt < 4; mt++) {
        int o = mt * 16 + (lane >> 2);
        float b0 = __ldg(&g_B4[o]), b1 = __ldg(&g_B4[o + 8]);
#pragma unroll
        for (int nb = 0; nb < 2; nb++) {
            int t = t0 + w * 16 + nb * 8 + (lane & 3) * 2;
            float* po = &out[((size_t)n * 2048 + t) * 64];
            float a0 = C4[mt][nb][0] + b0, a1 = C4[mt][nb][1] + b0;
            float a2 = C4[mt][nb][2] + b1, a3 = C4[mt][nb][3] + b1;
            po[o] = a0 > 0.f ? a0 : 0.01f * a0;
            po[64 + o] = a1 > 0.f ? a1 : 0.01f * a1;
            po[o + 8] = a2 > 0.f ? a2 : 0.01f * a2;
            po[64 + o + 8] = a3 > 0.f ? a3 : 0.01f * a3;
        }
    }
}

// ---------------- launch ----------------
extern "C" void kernel_launch(void* const* d_in, const int* in_sizes, int n_in,
                              void* d_out, int out_size) {
    (void)in_sizes; (void)n_in; (void)out_size;
    const float* poses = (const float*)d_in[0];
    const float* A1 = (const float*)d_in[1];
    const float* A2 = (const float*)d_in[2];
    const float* w1 = (const float*)d_in[3];
    const float* b1 = (const float*)d_in[4];
    const float* g1 = (const float*)d_in[5];
    const float* be1 = (const float*)d_in[6];
    const float* m1 = (const float*)d_in[7];
    const float* v1 = (const float*)d_in[8];
    const float* w2 = (const float*)d_in[9];
    const float* b2 = (const float*)d_in[10];
    const float* g2 = (const float*)d_in[11];
    const float* be2 = (const float*)d_in[12];
    const float* m2 = (const float*)d_in[13];
    const float* v2 = (const float*)d_in[14];
    const float* w3 = (const float*)d_in[15];
    const float* b3 = (const float*)d_in[16];
    const float* g3 = (const float*)d_in[17];
    const float* be3 = (const float*)d_in[18];
    const float* m3 = (const float*)d_in[19];
    const float* v3 = (const float*)d_in[20];
    const float* w4 = (const float*)d_in[21];
    const float* b4 = (const float*)d_in[22];
    const float* g4 = (const float*)d_in[23];
    const float* be4 = (const float*)d_in[24];
    const float* m4 = (const float*)d_in[25];
    const float* v4 = (const float*)d_in[26];
    float* out = (float*)d_out;

    size_t sm1 = 83712;
    size_t sm2 = K2_WSZ + 2 * K2_XB;   // 34560
    size_t sm34 = 104832;
    cudaFuncSetAttribute(k1, cudaFuncAttributeMaxDynamicSharedMemorySize, (int)sm1);
    cudaFuncSetAttribute(k2, cudaFuncAttributeMaxDynamicSharedMemorySize, (int)sm2);
    cudaFuncSetAttribute(k34, cudaFuncAttributeMaxDynamicSharedMemorySize, (int)sm34);

    prepAll<<<627, 256>>>(poses,
                          A1, w1, b1, g1, be1, m1, v1,
                          A2, w2, b2, g2, be2, m2, v2,
                          w3, b3, g3, be3, m3, v3,
                          w4, b4, g4, be4, m4, v4);
    k1<<<dim3(8, 16, 4), 256, sm1>>>();
    k2<<<dim3(8, 16, 2), 256, sm2>>>();
    k34<<<dim3(16, 16), 256, sm34>>>(out);
}

// round 15
// speedup vs baseline: 1.9459x; 1.1623x over previous
#include <cuda_runtime.h>
#include <cuda_fp16.h>

#define EPSV 1e-5f

// ---------------- device scratch ----------------
__device__ __align__(16) unsigned short g_W1h[36 * 17 * 16 * 24];   // fp16
__device__ __align__(16) unsigned short g_W2h[153 * 6 * 16 * 24];   // fp16
__device__ __align__(16) unsigned short g_W3t[30 * 16 * 24];        // fp16 f3 tiles
__device__ __align__(16) unsigned short g_W4f[12 * 16 * 24];        // fp16 f4 tiles
__device__ float g_B1[272];
__device__ float g_B2[96];
__device__ float g_B3[16];
__device__ float g_B4[64];
__device__ __align__(16) unsigned short g_Ph[16 * 2048 * 64];       // poses single fp16
__device__ __align__(16) unsigned short g_f1t[16 * 2048 * 288];     // f1 fp16 transposed [n][t][ch]
__device__ float g_f2[16 * 96 * 2048];
__device__ float g_f2b[16 * 96 * 2048];

__constant__ int c_part_of[17] = {1,2,3,1,1,4,4,5,5,2,2,3,3,0,0,0,0};
__constant__ int c_idx_of[17]  = {0,0,0,1,2,0,1,0,1,1,2,1,2,0,1,2,3};
__constant__ int c_len_of[6]   = {4,3,3,3,2,2};

// ---------------- helpers ----------------
__device__ __forceinline__ void split_fp16(float x, unsigned short& h, unsigned short& l) {
    __half hh = __float2half_rn(x);
    float r = x - __half2float(hh);
    __half ll = __float2half_rn(r);
    h = __half_as_ushort(hh); l = __half_as_ushort(ll);
}
__device__ __forceinline__ void ldsm4(unsigned r[4], const void* p) {
    unsigned a = (unsigned)__cvta_generic_to_shared(p);
    asm volatile("ldmatrix.sync.aligned.m8n8.x4.shared.b16 {%0,%1,%2,%3},[%4];"
                 : "=r"(r[0]), "=r"(r[1]), "=r"(r[2]), "=r"(r[3]) : "r"(a));
}
__device__ __forceinline__ void mma_fp16(float* c, const unsigned* a, unsigned b0, unsigned b1) {
    asm volatile("mma.sync.aligned.m16n8k16.row.col.f32.f16.f16.f32 "
                 "{%0,%1,%2,%3},{%4,%5,%6,%7},{%8,%9},{%0,%1,%2,%3};"
                 : "+f"(c[0]), "+f"(c[1]), "+f"(c[2]), "+f"(c[3])
                 : "r"(a[0]), "r"(a[1]), "r"(a[2]), "r"(a[3]), "r"(b0), "r"(b1));
}
__device__ __forceinline__ void cpa16(void* dst, const void* src) {
    unsigned d = (unsigned)__cvta_generic_to_shared(dst);
    asm volatile("cp.async.cg.shared.global [%0], [%1], 16;" :: "r"(d), "l"(src));
}
__device__ __forceinline__ void cpa16z(void* dst, const void* src, bool valid) {
    unsigned d = (unsigned)__cvta_generic_to_shared(dst);
    int sz = valid ? 16 : 0;
    asm volatile("cp.async.cg.shared.global [%0], [%1], 16, %2;" :: "r"(d), "l"(src), "r"(sz));
}
#define CP_COMMIT() asm volatile("cp.async.commit_group;")
#define CP_WAIT0()  asm volatile("cp.async.wait_group 0;")

// ---------------- fused prep (627 blocks x 256 thr) ----------------
__global__ void prepAll(const float* __restrict__ poses,
                        const float* __restrict__ A1, const float* __restrict__ w1,
                        const float* __restrict__ b1, const float* __restrict__ g1,
                        const float* __restrict__ be1, const float* __restrict__ m1,
                        const float* __restrict__ v1,
                        const float* __restrict__ A2, const float* __restrict__ w2,
                        const float* __restrict__ b2, const float* __restrict__ g2,
                        const float* __restrict__ be2, const float* __restrict__ m2,
                        const float* __restrict__ v2,
                        const float* __restrict__ w3, const float* __restrict__ b3,
                        const float* __restrict__ g3, const float* __restrict__ be3,
                        const float* __restrict__ m3, const float* __restrict__ v3,
                        const float* __restrict__ w4, const float* __restrict__ b4,
                        const float* __restrict__ g4, const float* __restrict__ be4,
                        const float* __restrict__ m4, const float* __restrict__ v4) {
    const int bid = blockIdx.x;
    if (bid < 256) {
        const int n = bid >> 4, tb = (bid & 15) * 128;
        for (int idx = threadIdx.x; idx < 128 * 64; idx += 256) {
            int tl = idx >> 6, col = idx & 63;
            int t = tb + tl;
            float v = (col < 51) ? poses[((size_t)n * 2048 + t) * 51 + col] : 0.f;
            g_Ph[((size_t)n * 2048 + t) * 64 + col] = __half_as_ushort(__float2half_rn(v));
        }
    } else if (bid < 528) {
        int cw = bid - 256;
        int c = cw / 17, w = cw % 17;
        int mt = cw >> 4, row = cw & 15;
        float s = g1[cw] * rsqrtf(v1[cw] + EPSV);
        for (int e = threadIdx.x; e < 36 * 24; e += 256) {
            int it = e / 24, col = e % 24;
            int dt = it >> 2, rc = it & 3;
            int r = rc * 16 + col;
            float val = 0.f;
            if (col < 16 && r < 51) {
                int u = r / 3, ci = r % 3;
                for (int k = 0; k < 5; k++)
                    for (int dv = 0; dv < 5; dv++) {
                        int v = u - dv + 2;
                        if (v >= 0 && v < 17)
                            val += A1[(k * 17 + v) * 17 + w] *
                                   w1[(((k * 16 + c) * 3 + ci) * 9 + dt) * 5 + dv];
                    }
                val *= s;
            }
            g_W1h[((it * 17 + mt) * 16 + row) * 24 + col] =
                __half_as_ushort(__float2half_rn(val));
        }
        if (threadIdx.x == 0) {
            float bias = 0.f;
            for (int k = 0; k < 5; k++) {
                float sa = 0.f;
                for (int v = 0; v < 17; v++) sa += A1[(k * 17 + v) * 17 + w];
                bias += b1[k * 16 + c] * sa;
            }
            g_B1[cw] = (bias - m1[cw]) * s + be1[cw];
        }
    } else if (bid < 624) {
        int cw = bid - 528;
        int c = cw / 6, w = cw % 6;
        int mt = cw >> 4, row = cw & 15;
        float s = g2[cw] * rsqrtf(v2[cw] + EPSV);
        for (int e = threadIdx.x; e < 153 * 24; e += 256) {
            int it = e / 24, col = e % 24;
            int cc = it / 9, dt = it % 9;
            int ch = cc * 16 + col;
            float val = 0.f;
            if (col < 16) {
                int f = ch / 17, jt = ch % 17;
                int p = c_part_of[jt], j = c_idx_of[jt], ln = c_len_of[p];
                int ci = f * ln + j;
                for (int k = 0; k < 5; k++)
                    for (int v = 0; v < 6; v++) {
                        int dp = p - v + 1;
                        if (dp >= 0 && dp < 3)
                            val += A2[(k * 6 + v) * 6 + w] *
                                   w2[(((k * 16 + c) * 64 + ci) * 9 + dt) * 3 + dp];
                    }
                val *= s;
            }
            g_W2h[((it * 6 + mt) * 16 + row) * 24 + col] =
                __half_as_ushort(__float2half_rn(val));
        }
        if (threadIdx.x == 0) {
            float bias = 0.f;
            for (int k = 0; k < 5; k++) {
                float sa = 0.f;
                for (int v = 0; v < 6; v++) sa += A2[(k * 6 + v) * 6 + w];
                bias += b2[k * 16 + c] * sa;
            }
            g_B2[cw] = (bias - m2[cw]) * s + be2[cw];
        }
    } else if (bid < 625) {
        for (int e = threadIdx.x; e < 12 * 384; e += 256) {
            int ti = e / 384, rem = e - ti * 384;
            int o = rem / 24, col = rem % 24;
            int dk = ti >> 2, mt = ti & 3;
            float val = 0.f;
            if (col < 16) {
                int og = mt * 16 + o;
                val = w4[og * 48 + col * 3 + dk] * (g4[og] * rsqrtf(v4[og] + EPSV));
            }
            g_W4f[(ti * 16 + o) * 24 + col] = __half_as_ushort(__float2half_rn(val));
        }
        if (threadIdx.x < 16) {
            int o = threadIdx.x;
            float s = g3[o] * rsqrtf(v3[o] + EPSV);
            g_B3[o] = (b3[o] - m3[o]) * s + be3[o];
        }
        if (threadIdx.x >= 32 && threadIdx.x < 96) {
            int o = threadIdx.x - 32;
            float s = g4[o] * rsqrtf(v4[o] + EPSV);
            g_B4[o] = (b4[o] - m4[o]) * s + be4[o];
        }
    } else {
        int half = bid - 625;  // 0,1
        for (int e = half * 5760 + threadIdx.x; e < half * 5760 + 5760; e += 256) {
            int ck = e / 384, rem = e - ck * 384;
            int o = rem / 24, col = rem % 24;
            int cc = ck / 5, dt = ck % 5;
            float val = 0.f;
            if (col < 16) {
                float s = g3[o] * rsqrtf(v3[o] + EPSV);
                val = w3[o * 480 + (cc * 16 + col) * 5 + dt] * s;
            }
            g_W3t[(ck * 16 + o) * 24 + col] = __half_as_ushort(__float2half_rn(val));
        }
    }
}

// ---------------- stage 1 tensor GEMM (fp16 1-term; transposed fp16 output) ----------------
// smem: Wbuf0 3840 | Wbuf1 3840 | Xh 38016 (epilogue T[256][88] = 45056) -> sm1 = 52736
#define K1_XOFF 7680
__global__ void __launch_bounds__(256, 2) k1() {
    extern __shared__ char sm[];
    const int n = blockIdx.y, t0 = blockIdx.x * 256;
    const int z = blockIdx.z;
    const int mt0 = (z == 0) ? 0 : 1 + z * 4;
    const int mcount = (z == 0) ? 5 : 4;
    const int tid = threadIdx.x, lane = tid & 31, w = tid >> 5;
    char* Xh = sm + K1_XOFF;

    auto prefW = [&](int it, char* buf) {
        const char* srcH = (const char*)(g_W1h + (size_t)(it * 17 + mt0) * 384);
        int cnt = mcount * 48;
        for (int i = tid; i < cnt; i += 256) cpa16(buf + i * 16, srcH + i * 16);
    };
    for (int i = tid; i < 264 * 8; i += 256) {
        int row = i >> 3, q = i & 7;
        int t = t0 - 4 + row;
        bool valid = (t >= 0 && t < 2048);
        size_t so = ((size_t)n * 2048 + (valid ? t : 0)) * 64 + q * 8;
        cpa16z(Xh + row * 144 + q * 16, g_Ph + so, valid);
    }
    prefW(0, sm); CP_COMMIT();

    float C[5][4][4];
#pragma unroll
    for (int i = 0; i < 5; i++)
#pragma unroll
        for (int j = 0; j < 4; j++)
#pragma unroll
            for (int q = 0; q < 4; q++) C[i][j][q] = 0.f;
    const int lrow = (lane & 15) * 48 + (lane >> 4) * 16;

    for (int it = 0; it < 36; it++) {
        char* buf = sm + (it & 1) * 3840;
        CP_WAIT0();
        __syncthreads();
        if (it + 1 < 36) { prefW(it + 1, sm + ((it + 1) & 1) * 3840); CP_COMMIT(); }
        const int dt = it >> 2, rc = it & 3;
        const int colb = (rc * 16 + (lane & 3) * 2) * 2;
        unsigned bh[4][2];
#pragma unroll
        for (int nb = 0; nb < 4; nb++) {
            int tt = w * 32 + nb * 8 + (lane >> 2) + dt;
            const char* ph = Xh + tt * 144 + colb;
            bh[nb][0] = *(const unsigned*)ph; bh[nb][1] = *(const unsigned*)(ph + 16);
        }
        for (int mi = 0; mi < mcount; mi++) {
            unsigned Ah[4];
            ldsm4(Ah, buf + mi * 768 + lrow);
#pragma unroll
            for (int nb = 0; nb < 4; nb++)
                mma_fp16(C[mi][nb], Ah, bh[nb][0], bh[nb][1]);
        }
    }

    // epilogue: stage transposed [t][ch] fp16 tile in smem, then coalesced STG.128
    __syncthreads();
    unsigned short* T = (unsigned short*)(sm + K1_XOFF);   // [256][88]
    for (int mi = 0; mi < mcount; mi++) {
        int chl = mi * 16 + (lane >> 2);
        float b0 = g_B1[mt0 * 16 + chl], b1 = g_B1[mt0 * 16 + chl + 8];
#pragma unroll
        for (int nb = 0; nb < 4; nb++) {
            int tl = w * 32 + nb * 8 + (lane & 3) * 2;
            T[tl * 88 + chl]           = __half_as_ushort(__float2half_rn(C[mi][nb][0] + b0));
            T[(tl + 1) * 88 + chl]     = __half_as_ushort(__float2half_rn(C[mi][nb][1] + b0));
            T[tl * 88 + chl + 8]       = __half_as_ushort(__float2half_rn(C[mi][nb][2] + b1));
            T[(tl + 1) * 88 + chl + 8] = __half_as_ushort(__float2half_rn(C[mi][nb][3] + b1));
        }
    }
    __syncthreads();
    const int ncp = mcount * 2;
    for (int idx = tid; idx < 256 * ncp; idx += 256) {
        int row = idx / ncp, cp = idx - row * ncp;
        uint4 v = *(const uint4*)(T + row * 88 + cp * 8);
        *(uint4*)&g_f1t[((size_t)n * 2048 + t0 + row) * 288 + mt0 * 16 + cp * 8] = v;
    }
}

// ---------------- stage 2 tensor GEMM (fp16 1-term, cp.async X, K-split over z) ----------------
#define K2_WSZ 9216
#define K2_XB  12672
__global__ void __launch_bounds__(256, 2) k2() {
    extern __shared__ char sm[];
    const int n = blockIdx.y, t0 = blockIdx.x * 256;
    const int zz = blockIdx.z;
    const int cc0 = zz ? 9 : 0;
    const int ncc = zz ? 8 : 9;
    const int tid = threadIdx.x, lane = tid & 31, w = tid >> 5;

    auto prefW = [&](int it, char* buf) {
        const char* srcH = (const char*)(g_W2h + (size_t)it * 2304);
        for (int i = tid; i < 288; i += 256) cpa16(buf + i * 16, srcH + i * 16);
    };
    auto prefX = [&](int cc, int buf) {
        char* dst = sm + K2_WSZ + buf * K2_XB;
        for (int r = tid; r < 264; r += 256) {
            int t = t0 - 4 + r;
            bool valid = (t >= 0 && t < 2048);
            const unsigned short* src =
                g_f1t + ((size_t)n * 2048 + (valid ? t : 0)) * 288 + cc * 16;
            cpa16z(dst + r * 48, src, valid);
            cpa16z(dst + r * 48 + 16, src + 8, valid);
        }
    };

    prefX(cc0, 0);
    prefW(cc0 * 9, sm);
    CP_COMMIT();

    float C[6][4][4];
#pragma unroll
    for (int i = 0; i < 6; i++)
#pragma unroll
        for (int j = 0; j < 4; j++)
#pragma unroll
            for (int q = 0; q < 4; q++) C[i][j][q] = 0.f;

    const int lrow = (lane & 15) * 48 + (lane >> 4) * 16;
    const int colb = (lane & 3) * 4;
    const int nit = ncc * 9;

    for (int i = 0; i < nit; i++) {
        const int ccl = i / 9, dt = i - ccl * 9;
        char* buf = sm + (i & 1) * 4608;
        CP_WAIT0();
        __syncthreads();
        if (i + 1 < nit) { prefW(cc0 * 9 + i + 1, sm + ((i + 1) & 1) * 4608); }
        if (dt == 0 && ccl + 1 < ncc) prefX(cc0 + ccl + 1, (ccl + 1) & 1);
        if (i + 1 < nit) CP_COMMIT();

        const char* Xb = sm + K2_WSZ + (ccl & 1) * K2_XB;
        unsigned bh[4][2];
#pragma unroll
        for (int nb = 0; nb < 4; nb++) {
            int tt = w * 32 + nb * 8 + (lane >> 2) + dt;
            const char* ph = Xb + tt * 48 + colb;
            bh[nb][0] = *(const unsigned*)ph; bh[nb][1] = *(const unsigned*)(ph + 16);
        }
#pragma unroll
        for (int mi = 0; mi < 6; mi++) {
            unsigned Ah[4];
            ldsm4(Ah, buf + mi * 768 + lrow);
#pragma unroll
            for (int nb = 0; nb < 4; nb++)
                mma_fp16(C[mi][nb], Ah, bh[nb][0], bh[nb][1]);
        }
    }

    float* dst = zz ? g_f2b : g_f2;
#pragma unroll
    for (int mi = 0; mi < 6; mi++) {
#pragma unroll
        for (int nb = 0; nb < 4; nb++) {
            int ch0 = mi * 16 + (lane >> 2);
            int tt = t0 + w * 32 + nb * 8 + (lane & 3) * 2;
            float b0 = zz ? 0.f : g_B2[ch0];
            float b1 = zz ? 0.f : g_B2[ch0 + 8];
            float2 v0 = make_float2(C[mi][nb][0] + b0, C[mi][nb][1] + b0);
            float2 v1 = make_float2(C[mi][nb][2] + b1, C[mi][nb][3] + b1);
            *(float2*)&dst[((size_t)n * 96 + ch0) * 2048 + tt] = v0;
            *(float2*)&dst[((size_t)n * 96 + ch0 + 8) * 2048 + tt] = v1;
        }
    }
}

// ---------------- stages 3+4: both tensorized ----------------
#define S_XL   29952
#define S_WT3  59904
#define S_W4F  82944
#define S_F3H  92160
#define S_F3L  98496
__global__ void __launch_bounds__(256, 2) k34(float* __restrict__ out) {
    extern __shared__ char smc[];
    unsigned short* Xh = (unsigned short*)smc;
    unsigned short* Xl = (unsigned short*)(smc + S_XL);
    char* Wt = smc + S_WT3;
    char* W4 = smc + S_W4F;
    unsigned short* F3h = (unsigned short*)(smc + S_F3H);
    unsigned short* F3l = (unsigned short*)(smc + S_F3L);
    const int n = blockIdx.y;
    const int t0 = blockIdx.x * 128;
    const int tid = threadIdx.x, lane = tid & 31, w = tid >> 5;

    for (int i = tid; i < 1440; i += 256) cpa16(Wt + i * 16, (const char*)g_W3t + i * 16);
    for (int i = tid; i < 576; i += 256) cpa16(W4 + i * 16, (const char*)g_W4f + i * 16);
    CP_COMMIT();

    for (int idx = tid; idx < 96 * 144; idx += 256) {
        int ch = idx / 144, xr = idx - ch * 144;
        int t = t0 - 4 + xr;
        float v = 0.f;
        if (t >= 0 && t < 2048) {
            size_t o = ((size_t)n * 96 + ch) * 2048 + t;
            v = g_f2[o] + g_f2b[o];
        }
        unsigned short h, l; split_fp16(v, h, l);
        Xh[xr * 104 + ch] = h; Xl[xr * 104 + ch] = l;
    }
    CP_WAIT0();
    __syncthreads();

    float C[3][4];
#pragma unroll
    for (int q = 0; q < 3; q++)
#pragma unroll
        for (int j = 0; j < 4; j++) C[q][j] = 0.f;
    const int nnb = (w == 0) ? 3 : 2;
    int nbs[3]; nbs[0] = w; nbs[1] = 8 + w; nbs[2] = 16;
    const int lrow = (lane & 15) * 48 + (lane >> 4) * 16;

    for (int ck = 0; ck < 30; ck++) {
        const int cc = ck / 5, dt = ck % 5;
        unsigned A[4];
        ldsm4(A, Wt + ck * 768 + lrow);
#pragma unroll
        for (int q = 0; q < 3; q++) {
            if (q >= nnb) break;
            int xr = nbs[q] * 8 + (lane >> 2) + dt + 1;
            const char* ph = (const char*)Xh + xr * 208 + cc * 32 + (lane & 3) * 4;
            const char* pl = (const char*)Xl + xr * 208 + cc * 32 + (lane & 3) * 4;
            mma_fp16(C[q], A, *(const unsigned*)ph, *(const unsigned*)(ph + 16));
            mma_fp16(C[q], A, *(const unsigned*)pl, *(const unsigned*)(pl + 16));
        }
    }
    {
        int o0 = lane >> 2;
        float bb0 = __ldg(&g_B3[o0]), bb1 = __ldg(&g_B3[o0 + 8]);
#pragma unroll
        for (int q = 0; q < 3; q++) {
            if (q >= nnb) break;
            int s0 = nbs[q] * 8 + (lane & 3) * 2;
#pragma unroll
            for (int j = 0; j < 2; j++) {
                int s = s0 + j;
                if (s < 132) {
                    int t3 = t0 - 1 + s;
                    bool ok = (t3 >= 0 && t3 < 2048);
                    float a = C[q][j] + bb0;
                    float b = C[q][2 + j] + bb1;
                    float va = ok ? (a > 0.f ? a : 0.01f * a) : 0.f;
                    float vb = ok ? (b > 0.f ? b : 0.01f * b) : 0.f;
                    unsigned short h, l;
                    split_fp16(va, h, l);
                    F3h[s * 24 + o0] = h; F3l[s * 24 + o0] = l;
                    split_fp16(vb, h, l);
                    F3h[s * 24 + o0 + 8] = h; F3l[s * 24 + o0 + 8] = l;
                }
            }
        }
    }
    __syncthreads();

    float C4[4][2][4];
#pragma unroll
    for (int mt = 0; mt < 4; mt++)
#pragma unroll
        for (int nb = 0; nb < 2; nb++)
#pragma unroll
            for (int j = 0; j < 4; j++) C4[mt][nb][j] = 0.f;

    for (int dk = 0; dk < 3; dk++) {
        unsigned bh[2][2], bl[2][2];
#pragma unroll
        for (int nb = 0; nb < 2; nb++) {
            int row = w * 16 + nb * 8 + (lane >> 2) + dk;
            const char* ph = (const char*)F3h + row * 48 + (lane & 3) * 4;
            const char* pl = (const char*)F3l + row * 48 + (lane & 3) * 4;
            bh[nb][0] = *(const unsigned*)ph; bh[nb][1] = *(const unsigned*)(ph + 16);
            bl[nb][0] = *(const unsigned*)pl; bl[nb][1] = *(const unsigned*)(pl + 16);
        }
#pragma unroll
        for (int mt = 0; mt < 4; mt++) {
            unsigned A[4];
            ldsm4(A, W4 + (dk * 4 + mt) * 768 + lrow);
#pragma unroll
            for (int nb = 0; nb < 2; nb++) {
                mma_fp16(C4[mt][nb], A, bh[nb][0], bh[nb][1]);
                mma_fp16(C4[mt][nb], A, bl[nb][0], bl[nb][1]);
            }
        }
    }
#pragma unroll
    for (int mt = 0; mt < 4; mt++) {
        int o = mt * 16 + (lane >> 2);
        float b0 = __ldg(&g_B4[o]), b1 = __ldg(&g_B4[o + 8]);
#pragma unroll
        for (int nb = 0; nb < 2; nb++) {
            int t = t0 + w * 16 + nb * 8 + (lane & 3) * 2;
            float* po = &out[((size_t)n * 2048 + t) * 64];
            float a0 = C4[mt][nb][0] + b0, a1 = C4[mt][nb][1] + b0;
            float a2 = C4[mt][nb][2] + b1, a3 = C4[mt][nb][3] + b1;
            po[o] = a0 > 0.f ? a0 : 0.01f * a0;
            po[64 + o] = a1 > 0.f ? a1 : 0.01f * a1;
            po[o + 8] = a2 > 0.f ? a2 : 0.01f * a2;
            po[64 + o + 8] = a3 > 0.f ? a3 : 0.01f * a3;
        }
    }
}

// ---------------- launch ----------------
extern "C" void kernel_launch(void* const* d_in, const int* in_sizes, int n_in,
                              void* d_out, int out_size) {
    (void)in_sizes; (void)n_in; (void)out_size;
    const float* poses = (const float*)d_in[0];
    const float* A1 = (const float*)d_in[1];
    const float* A2 = (const float*)d_in[2];
    const float* w1 = (const float*)d_in[3];
    const float* b1 = (const float*)d_in[4];
    const float* g1 = (const float*)d_in[5];
    const float* be1 = (const float*)d_in[6];
    const float* m1 = (const float*)d_in[7];
    const float* v1 = (const float*)d_in[8];
    const float* w2 = (const float*)d_in[9];
    const float* b2 = (const float*)d_in[10];
    const float* g2 = (const float*)d_in[11];
    const float* be2 = (const float*)d_in[12];
    const float* m2 = (const float*)d_in[13];
    const float* v2 = (const float*)d_in[14];
    const float* w3 = (const float*)d_in[15];
    const float* b3 = (const float*)d_in[16];
    const float* g3 = (const float*)d_in[17];
    const float* be3 = (const float*)d_in[18];
    const float* m3 = (const float*)d_in[19];
    const float* v3 = (const float*)d_in[20];
    const float* w4 = (const float*)d_in[21];
    const float* b4 = (const float*)d_in[22];
    const float* g4 = (const float*)d_in[23];
    const float* be4 = (const float*)d_in[24];
    const float* m4 = (const float*)d_in[25];
    const float* v4 = (const float*)d_in[26];
    float* out = (float*)d_out;

    size_t sm1 = 52736;                // 7680 + T(45056)
    size_t sm2 = K2_WSZ + 2 * K2_XB;   // 34560
    size_t sm34 = 104832;
    cudaFuncSetAttribute(k1, cudaFuncAttributeMaxDynamicSharedMemorySize, (int)sm1);
    cudaFuncSetAttribute(k2, cudaFuncAttributeMaxDynamicSharedMemorySize, (int)sm2);
    cudaFuncSetAttribute(k34, cudaFuncAttributeMaxDynamicSharedMemorySize, (int)sm34);

    prepAll<<<627, 256>>>(poses,
                          A1, w1, b1, g1, be1, m1, v1,
                          A2, w2, b2, g2, be2, m2, v2,
                          w3, b3, g3, be3, m3, v3,
                          w4, b4, g4, be4, m4, v4);
    k1<<<dim3(8, 16, 4), 256, sm1>>>();
    k2<<<dim3(8, 16, 2), 256, sm2>>>();
    k34<<<dim3(16, 16), 256, sm34>>>(out);
}